// round 14
// baseline (speedup 1.0000x reference)
#include <cuda_runtime.h>
#include <cuda_bf16.h>
#include <cuda_fp16.h>
#include <math.h>

#define NB   2
#define NS   2048
#define NDM  1024
#define NH   16
#define NDK  64
#define NM   (NB * NS)   // 4096 rows
#define ASZ  ((size_t)NM * NDM)
#define WSZ  ((size_t)NDM * NDM)

// log2(e)/8: folds 1/sqrt(64) attention scale AND exp->ex2 (applied to K)
#define QSCALE 0.18033688011111366f

// Scratch (allocation-free rule: __device__ globals)
__device__ __align__(16) __half g_xs[ASZ];        // hidden states fp16 single
__device__ __align__(16) __half g_w16[4 * WSZ];   // Wq,Wk,Wv,Wo fp16
__device__ __align__(16) __half g_q16h[ASZ];      // Q fp16 pair (pre-rope)
__device__ __align__(16) __half g_q16l[ASZ];
__device__ __align__(16) __half g_k16h[ASZ];      // K fp16 pair (pre-rope)
__device__ __align__(16) __half g_k16l[ASZ];
__device__ __align__(16) __half g_qs[ASZ];        // Q post-rope single
__device__ __align__(16) __half g_kvv[2 * ASZ];   // [K(post-rope,scaled) | V]
__device__ __align__(16) __half g_ct[ASZ];        // ctx single fp16

// ---------------------------------------------------------------------------
// helpers
// ---------------------------------------------------------------------------
__device__ __forceinline__ void ldsm4(unsigned addr, unsigned& r0, unsigned& r1,
                                      unsigned& r2, unsigned& r3)
{
    asm volatile("ldmatrix.sync.aligned.m8n8.x4.shared.b16 {%0,%1,%2,%3}, [%4];"
                 : "=r"(r0), "=r"(r1), "=r"(r2), "=r"(r3) : "r"(addr));
}
__device__ __forceinline__ void ldsm4t(unsigned addr, unsigned& r0, unsigned& r1,
                                       unsigned& r2, unsigned& r3)
{
    asm volatile("ldmatrix.sync.aligned.m8n8.x4.trans.shared.b16 {%0,%1,%2,%3}, [%4];"
                 : "=r"(r0), "=r"(r1), "=r"(r2), "=r"(r3) : "r"(addr));
}
__device__ __forceinline__ void mma_f16(float* d, unsigned a0, unsigned a1,
                                        unsigned a2, unsigned a3,
                                        unsigned b0, unsigned b1)
{
    asm volatile("mma.sync.aligned.m16n8k16.row.col.f32.f16.f16.f32 "
                 "{%0,%1,%2,%3}, {%4,%5,%6,%7}, {%8,%9}, {%0,%1,%2,%3};"
                 : "+f"(d[0]), "+f"(d[1]), "+f"(d[2]), "+f"(d[3])
                 : "r"(a0), "r"(a1), "r"(a2), "r"(a3), "r"(b0), "r"(b1));
}
__device__ __forceinline__ unsigned packhf2(float e0, float e1)
{
    __half2 h = __floats2half2_rn(e0, e1);
    return *reinterpret_cast<unsigned*>(&h);
}
__device__ __forceinline__ unsigned h2exp2u(unsigned x)
{
    unsigned r;
    asm("ex2.approx.f16x2 %0, %1;" : "=r"(r) : "r"(x));
    return r;
}
__device__ __forceinline__ void store_pair16(__half* H, __half* L, size_t idx,
                                             float f0, float f1)
{
    __half2 h2 = __floats2half2_rn(f0, f1);
    __half2 l2 = __floats2half2_rn(f0 - __low2float(h2), f1 - __high2float(h2));
    *reinterpret_cast<__half2*>(H + idx) = h2;
    *reinterpret_cast<__half2*>(L + idx) = l2;
}

// ---------------------------------------------------------------------------
// prep kernels (3 launches so QKV GEMM is launch index 3 for ncu)
// ---------------------------------------------------------------------------
__global__ __launch_bounds__(256) void prep_hs_kernel(const float* __restrict__ hs,
                                                      __half* __restrict__ xs)
{
    int i = blockIdx.x * 256 + threadIdx.x;       // over ASZ/4
    float4 v = reinterpret_cast<const float4*>(hs)[i];
    __half2 h0 = __floats2half2_rn(v.x, v.y);
    __half2 h1 = __floats2half2_rn(v.z, v.w);
    reinterpret_cast<uint2*>(xs)[i] = make_uint2(*(unsigned*)&h0, *(unsigned*)&h1);
}

__global__ __launch_bounds__(256) void prep_w2_kernel(const float* __restrict__ wa,
                                                      const float* __restrict__ wb,
                                                      __half* __restrict__ out)
{
    int i = blockIdx.x * 256 + threadIdx.x;       // over 2*WSZ/4 = 2^19
    int widx = i >> 18;
    int loc  = i & ((1 << 18) - 1);
    const float* w = widx ? wb : wa;
    float4 v = reinterpret_cast<const float4*>(w)[loc];
    __half2 h0 = __floats2half2_rn(v.x, v.y);
    __half2 h1 = __floats2half2_rn(v.z, v.w);
    reinterpret_cast<uint2*>(out + (size_t)widx * WSZ)[loc] =
        make_uint2(*(unsigned*)&h0, *(unsigned*)&h1);
}

// ---------------------------------------------------------------------------
// Tensor-core GEMM: Y = A[M,K] * B[N,K]^T, fp16 1-MMA.
// 128-thread CTA, block tile 128x128, 4 warps (2x2 grid, 64x64 each),
// 3-stage cp.async pipeline. ILP restructure: ALL 16 fragment ldsm
// (8 B + 8 A, both ks) issued up front, then a 64-MMA dependency-free burst
// -> ldsm latency overlapped instead of serialized per ks-phase.
// QKV=1: grid (24,32); widx=bx>>3 -> Q pair / K pair / V single outputs
// QKV=0: grid (8,32); f32 output (Wo)
// ---------------------------------------------------------------------------
#define BM 128
#define BN 128
#define BK 32
#define PITCH 40
#define G_BOFF  (128 * PITCH)               // B tile after A (128 rows each)
#define G_STG   (256 * PITCH)               // elems per stage
#define G_STG_B (G_STG * 2)                 // 20480 B
#define G_NSTG  3

template <int QKV>
__global__ __launch_bounds__(128, 2) void gemm_f16_kernel(
    const __half* __restrict__ A, const __half* __restrict__ Bbase,
    float* __restrict__ Y,
    __half* __restrict__ q16h, __half* __restrict__ q16l,
    __half* __restrict__ k16h, __half* __restrict__ k16l,
    __half* __restrict__ v16)
{
    const int K = NDM, N = NDM;
    extern __shared__ __align__(16) __half smem[];

    int t = threadIdx.x;
    int warp = t >> 5, lane = t & 31;
    int wm = warp >> 1, wn = warp & 1;      // 2 x 2 warp grid (64x64 tiles)
    int widx = QKV ? (blockIdx.x >> 3) : 0;
    int nblk = QKV ? (blockIdx.x & 7) : blockIdx.x;
    int m0 = blockIdx.y * BM;
    int n0 = nblk * BN;
    const __half* B = Bbase + (size_t)widx * WSZ;

    unsigned smem_base = (unsigned)__cvta_generic_to_shared(smem);

    // 8 x 16B cp.async chunks per thread per stage (A 128 rows, B 128 rows)
    const __half* gsrc[8];
    unsigned sdst[8];
#pragma unroll
    for (int i = 0; i < 8; i++) {
        int g = t + i * 128;
        const __half* base;
        int row, arr_off;
        if (g < 512) { base = A; row = g >> 2;          arr_off = 0;      }
        else         { base = B; row = (g - 512) >> 2;  arr_off = G_BOFF; }
        int c = g & 3;
        int rg = ((g < 512) ? m0 : n0) + row;
        gsrc[i] = base + (size_t)rg * K + c * 8;
        sdst[i] = smem_base + (unsigned)((arr_off + row * PITCH + c * 8) * 2);
    }

    float acc[4][8][4];
#pragma unroll
    for (int mt = 0; mt < 4; mt++)
#pragma unroll
        for (int nt = 0; nt < 8; nt++)
#pragma unroll
            for (int r = 0; r < 4; r++) acc[mt][nt][r] = 0.f;

    // prologue: stages 0 and 1
#pragma unroll
    for (int st = 0; st < G_NSTG - 1; st++) {
        unsigned soff = (unsigned)(st * G_STG_B);
        int koff = st * BK;
#pragma unroll
        for (int i = 0; i < 8; i++)
            asm volatile("cp.async.cg.shared.global [%0], [%1], 16;"
                         :: "r"(sdst[i] + soff), "l"(gsrc[i] + koff));
        asm volatile("cp.async.commit_group;");
    }

    const int NK = K / BK;  // 32
    int cur = 0;
    for (int it = 0; it < NK; it++) {
        if (it + 1 < NK) asm volatile("cp.async.wait_group 1;");
        else             asm volatile("cp.async.wait_group 0;");
        __syncthreads();

        if (it + 2 < NK) {
            int pf = cur + 2; if (pf >= G_NSTG) pf -= G_NSTG;
            unsigned soff = (unsigned)(pf * G_STG_B);
            int koff = (it + 2) * BK;
#pragma unroll
            for (int i = 0; i < 8; i++)
                asm volatile("cp.async.cg.shared.global [%0], [%1], 16;"
                             :: "r"(sdst[i] + soff), "l"(gsrc[i] + koff));
            asm volatile("cp.async.commit_group;");
        }

        unsigned sb = smem_base + (unsigned)(cur * G_STG_B);
        int lrow = lane & 15;
        int khi  = (lane & 16) ? 8 : 0;

        // ---- ALL fragment loads first (16 ldsm, latencies overlap) ----
        unsigned bh[2][8][2];
        unsigned av[2][4][4];
#pragma unroll
        for (int ks = 0; ks < 2; ks++) {
            int kof = ks * 16 + khi;
#pragma unroll
            for (int bn = 0; bn < 4; bn++) {
                int nrow = wn * 64 + bn * 16 + lrow;
                unsigned r0, r1, r2, r3;
                ldsm4(sb + (unsigned)((G_BOFF + nrow * PITCH + kof) * 2), r0, r1, r2, r3);
                bh[ks][bn * 2][0] = r0; bh[ks][bn * 2 + 1][0] = r1;
                bh[ks][bn * 2][1] = r2; bh[ks][bn * 2 + 1][1] = r3;
            }
#pragma unroll
            for (int mt = 0; mt < 4; mt++) {
                int mrow = wm * 64 + mt * 16 + lrow;
                ldsm4(sb + (unsigned)((mrow * PITCH + kof) * 2),
                      av[ks][mt][0], av[ks][mt][1], av[ks][mt][2], av[ks][mt][3]);
            }
        }
        // ---- 64-MMA burst (no smem dependencies inside) ----
#pragma unroll
        for (int ks = 0; ks < 2; ks++)
#pragma unroll
            for (int mt = 0; mt < 4; mt++)
#pragma unroll
                for (int nt = 0; nt < 8; nt++)
                    mma_f16(acc[mt][nt],
                            av[ks][mt][0], av[ks][mt][1], av[ks][mt][2], av[ks][mt][3],
                            bh[ks][nt][0], bh[ks][nt][1]);

        cur++; if (cur == G_NSTG) cur = 0;
    }

#pragma unroll
    for (int mt = 0; mt < 4; mt++) {
        int r = m0 + wm * 64 + mt * 16 + (lane >> 2);
#pragma unroll
        for (int nt = 0; nt < 8; nt++) {
            int cc = n0 + wn * 64 + nt * 8 + (lane & 3) * 2;
#pragma unroll
            for (int half = 0; half < 2; half++) {
                size_t idx = (size_t)(r + half * 8) * N + cc;
                float f0 = acc[mt][nt][half * 2], f1 = acc[mt][nt][half * 2 + 1];
                if (QKV == 0) {
                    *reinterpret_cast<float2*>(&Y[idx]) = make_float2(f0, f1);
                } else if (widx == 0) {
                    store_pair16(q16h, q16l, idx, f0, f1);
                } else if (widx == 1) {
                    store_pair16(k16h, k16l, idx, f0, f1);
                } else {
                    __half2 h2 = __floats2half2_rn(f0, f1);
                    *reinterpret_cast<__half2*>(v16 + idx) = h2;
                }
            }
        }
    }
}

// ---------------------------------------------------------------------------
// RoPE, fully parallel: one thread per (m, h, i<32).
// ---------------------------------------------------------------------------
__global__ __launch_bounds__(256) void rope_kernel(const int* __restrict__ pos)
{
    int idx = blockIdx.x * 256 + threadIdx.x;   // [0, 2M)
    int m = idx >> 9;
    int h = (idx >> 5) & 15;
    int i = idx & 31;

    float p = (float)pos[m];
    float freq = (float)exp(-(double)(2 * i) / 64.0 * 9.210340371976184);
    float ang = p * freq;
    float s, c;
    sincosf(ang, &s, &c);

    size_t base = (size_t)m * NDM + (size_t)h * NDK + i;
    float q0 = __half2float(g_q16h[base]) + __half2float(g_q16l[base]);
    float q1 = __half2float(g_q16h[base + 32]) + __half2float(g_q16l[base + 32]);
    g_qs[base]      = __float2half_rn(q0 * c - q1 * s);
    g_qs[base + 32] = __float2half_rn(q1 * c + q0 * s);

    float k0 = __half2float(g_k16h[base]) + __half2float(g_k16l[base]);
    float k1 = __half2float(g_k16h[base + 32]) + __half2float(g_k16l[base + 32]);
    g_kvv[base]      = __float2half_rn((k0 * c - k1 * s) * QSCALE);
    g_kvv[base + 32] = __float2half_rn((k1 * c + k0 * s) * QSCALE);
}

// ---------------------------------------------------------------------------
// Tensor-core flash attention, fp16, max-free softmax, 32 q-rows per warp.
// QK -> exp -> PV interleaved per 16-key block. 128 threads, 3 CTAs/SM.
// (unchanged from R12)
// ---------------------------------------------------------------------------
#define AP 72
#define AT_STAGE_E (2 * 64 * AP)
#define AT_STAGE_B (AT_STAGE_E * 2)       // 18432 B
#define K_OFF 0
#define V_OFF (64 * AP)
#define ONES2 0x3C003C00u                 // half2 (1.0, 1.0)

__global__ __launch_bounds__(128, 3) void attn_tc_kernel()
{
    extern __shared__ __align__(16) __half att_smem[];
    unsigned sbase = (unsigned)__cvta_generic_to_shared(att_smem);

    int t = threadIdx.x, lane = t & 31, warp = t >> 5;
    int qt = blockIdx.x, h = blockIdx.y, b = blockIdx.z;
    int g = lane >> 2, qr = lane & 3;

    unsigned aQ[2][4][4];
    size_t qbase[2];
#pragma unroll
    for (int mh = 0; mh < 2; mh++) {
        size_t qrow0 = (size_t)(b * NS + qt * 128 + warp * 32 + mh * 16 + g) * NDM
                     + (size_t)h * NDK;
        size_t qrow8 = qrow0 + 8 * NDM;
        qbase[mh] = qrow0;
#pragma unroll
        for (int kk = 0; kk < 4; kk++) {
            int kc = kk * 16 + qr * 2;
            aQ[mh][kk][0] = *reinterpret_cast<const unsigned*>(g_qs + qrow0 + kc);
            aQ[mh][kk][1] = *reinterpret_cast<const unsigned*>(g_qs + qrow8 + kc);
            aQ[mh][kk][2] = *reinterpret_cast<const unsigned*>(g_qs + qrow0 + kc + 8);
            aQ[mh][kk][3] = *reinterpret_cast<const unsigned*>(g_qs + qrow8 + kc + 8);
        }
    }

    const __half* gbase = g_kvv + (size_t)(b * NS) * NDM + (size_t)h * NDK;
    unsigned goffs[8];
    unsigned sdst[8];
#pragma unroll
    for (int i = 0; i < 8; i++) {
        int gi = t + i * 128;
        int arr = gi >> 9;            // 0=K 1=V
        int rw  = (gi & 511) >> 3;    // key row 0..63
        int c   = gi & 7;             // 16B chunk in 128B row
        goffs[i] = (unsigned)(arr * ASZ + (size_t)rw * NDM + c * 8);
        sdst[i] = sbase + (unsigned)((arr * 64 * AP + rw * AP + c * 8) * 2);
    }

    float o[2][8][4];
#pragma unroll
    for (int mh = 0; mh < 2; mh++)
#pragma unroll
        for (int j = 0; j < 8; j++)
#pragma unroll
            for (int r = 0; r < 4; r++) o[mh][j][r] = 0.f;
    float osum[2][4] = {{0.f, 0.f, 0.f, 0.f}, {0.f, 0.f, 0.f, 0.f}};

#pragma unroll
    for (int st = 0; st < 2; st++) {
        unsigned soff = (unsigned)(st * AT_STAGE_B);
        unsigned goff = (unsigned)(st * 64 * NDM);
#pragma unroll
        for (int i = 0; i < 8; i++)
            asm volatile("cp.async.cg.shared.global [%0], [%1], 16;"
                         :: "r"(sdst[i] + soff), "l"(gbase + goffs[i] + goff));
        asm volatile("cp.async.commit_group;");
    }

    const int NT = NS / 64;  // 32
    int cur = 0;
    for (int kt = 0; kt < NT; kt++) {
        if (kt + 1 < NT) asm volatile("cp.async.wait_group 1;");
        else             asm volatile("cp.async.wait_group 0;");
        __syncthreads();

        if (kt + 2 < NT) {
            int pf = cur + 2; if (pf >= 3) pf -= 3;
            unsigned soff = (unsigned)(pf * AT_STAGE_B);
            unsigned goff = (unsigned)((kt + 2) * 64 * NDM);
#pragma unroll
            for (int i = 0; i < 8; i++)
                asm volatile("cp.async.cg.shared.global [%0], [%1], 16;"
                             :: "r"(sdst[i] + soff), "l"(gbase + goffs[i] + goff));
            asm volatile("cp.async.commit_group;");
        }

        unsigned sb = sbase + (unsigned)(cur * AT_STAGE_B);
        int lr15 = lane & 15;
        int khi  = (lane & 16) ? 8 : 0;

#pragma unroll
        for (int u = 0; u < 4; u++) {
            float s0[4] = {0.f, 0.f, 0.f, 0.f};
            float s1[4] = {0.f, 0.f, 0.f, 0.f};
            float s2[4] = {0.f, 0.f, 0.f, 0.f};
            float s3[4] = {0.f, 0.f, 0.f, 0.f};
#pragma unroll
            for (int kk = 0; kk < 4; kk++) {
                unsigned addr = sb + (unsigned)((K_OFF + (u * 16 + lr15) * AP
                                                + kk * 16 + khi) * 2);
                unsigned k0, k1, k2, k3;
                ldsm4(addr, k0, k1, k2, k3);
                mma_f16(s0, aQ[0][kk][0], aQ[0][kk][1], aQ[0][kk][2], aQ[0][kk][3], k0, k2);
                mma_f16(s1, aQ[0][kk][0], aQ[0][kk][1], aQ[0][kk][2], aQ[0][kk][3], k1, k3);
                mma_f16(s2, aQ[1][kk][0], aQ[1][kk][1], aQ[1][kk][2], aQ[1][kk][3], k0, k2);
                mma_f16(s3, aQ[1][kk][0], aQ[1][kk][1], aQ[1][kk][2], aQ[1][kk][3], k1, k3);
            }

            unsigned ph0[4], ph1[4];
            ph0[0] = h2exp2u(packhf2(s0[0], s0[1]));
            ph0[1] = h2exp2u(packhf2(s0[2], s0[3]));
            ph0[2] = h2exp2u(packhf2(s1[0], s1[1]));
            ph0[3] = h2exp2u(packhf2(s1[2], s1[3]));
            ph1[0] = h2exp2u(packhf2(s2[0], s2[1]));
            ph1[1] = h2exp2u(packhf2(s2[2], s2[3]));
            ph1[2] = h2exp2u(packhf2(s3[0], s3[1]));
            ph1[3] = h2exp2u(packhf2(s3[2], s3[3]));

            mma_f16(osum[0], ph0[0], ph0[1], ph0[2], ph0[3], ONES2, ONES2);
            mma_f16(osum[1], ph1[0], ph1[1], ph1[2], ph1[3], ONES2, ONES2);

#pragma unroll
            for (int n0 = 0; n0 < 64; n0 += 16) {
                unsigned addr = sb + (unsigned)((V_OFF + (u * 16 + lr15) * AP
                                                + n0 + ((lane >> 4) & 1) * 8) * 2);
                unsigned v0, v1, v2, v3;
                ldsm4t(addr, v0, v1, v2, v3);
                int j = n0 >> 3;
                mma_f16(o[0][j],   ph0[0], ph0[1], ph0[2], ph0[3], v0, v1);
                mma_f16(o[0][j+1], ph0[0], ph0[1], ph0[2], ph0[3], v2, v3);
                mma_f16(o[1][j],   ph1[0], ph1[1], ph1[2], ph1[3], v0, v1);
                mma_f16(o[1][j+1], ph1[0], ph1[1], ph1[2], ph1[3], v2, v3);
            }
        }
        cur++; if (cur == 3) cur = 0;
    }

#pragma unroll
    for (int mh = 0; mh < 2; mh++) {
        float inv0 = 1.f / osum[mh][0], inv1 = 1.f / osum[mh][2];
        size_t orow0 = qbase[mh];
        size_t orow8 = orow0 + 8 * NDM;
#pragma unroll
        for (int j = 0; j < 8; j++) {
            int cc = j * 8 + qr * 2;
            __half2 h0 = __floats2half2_rn(o[mh][j][0] * inv0, o[mh][j][1] * inv0);
            __half2 h1 = __floats2half2_rn(o[mh][j][2] * inv1, o[mh][j][3] * inv1);
            *reinterpret_cast<__half2*>(g_ct + orow0 + cc) = h0;
            *reinterpret_cast<__half2*>(g_ct + orow8 + cc) = h1;
        }
    }
}

// ---------------------------------------------------------------------------
extern "C" void kernel_launch(void* const* d_in, const int* in_sizes, int n_in,
                              void* d_out, int out_size)
{
    const float* hs  = (const float*)d_in[0];
    const int*   pos = (const int*)  d_in[1];
    const float* Wq  = (const float*)d_in[2];
    const float* Wk  = (const float*)d_in[3];
    const float* Wv  = (const float*)d_in[4];
    const float* Wo  = (const float*)d_in[5];
    float* out = (float*)d_out;
    (void)in_sizes; (void)n_in; (void)out_size;

    __half *xs, *w16, *q16h, *q16l, *k16h, *k16l, *kvv, *ct;
    cudaGetSymbolAddress((void**)&xs,   g_xs);
    cudaGetSymbolAddress((void**)&w16,  g_w16);
    cudaGetSymbolAddress((void**)&q16h, g_q16h);
    cudaGetSymbolAddress((void**)&q16l, g_q16l);
    cudaGetSymbolAddress((void**)&k16h, g_k16h);
    cudaGetSymbolAddress((void**)&k16l, g_k16l);
    cudaGetSymbolAddress((void**)&kvv,  g_kvv);
    cudaGetSymbolAddress((void**)&ct,   g_ct);

    int gemm_smem = G_NSTG * G_STG_B;   // 61440 B
    cudaFuncSetAttribute(gemm_f16_kernel<1>,
                         cudaFuncAttributeMaxDynamicSharedMemorySize, gemm_smem);
    cudaFuncSetAttribute(gemm_f16_kernel<0>,
                         cudaFuncAttributeMaxDynamicSharedMemorySize, gemm_smem);

    // [0..2] prep (QKV GEMM lands at ncu slot 3)
    prep_hs_kernel<<<(int)(ASZ / 4 / 256), 256>>>(hs, xs);
    prep_w2_kernel<<<(int)(2 * WSZ / 4 / 256), 256>>>(Wq, Wk, w16);
    prep_w2_kernel<<<(int)(2 * WSZ / 4 / 256), 256>>>(Wv, Wo, w16 + 2 * WSZ);

    // [3] fused QKV projection  (<- ncu capture slot)
    gemm_f16_kernel<1><<<dim3(24, NM / BM), 128, gemm_smem>>>(
        xs, w16, nullptr, q16h, q16l, k16h, k16l, kvv + ASZ);

    // [4] rope
    rope_kernel<<<(NM * NH * 32) / 256, 256>>>(pos);

    // [5] attention
    int attn_smem = 3 * AT_STAGE_B;   // 55296 B
    cudaFuncSetAttribute(attn_tc_kernel,
                         cudaFuncAttributeMaxDynamicSharedMemorySize, attn_smem);
    attn_tc_kernel<<<dim3(NS / 128, NH, NB), 128, attn_smem>>>();

    // [6] output projection
    gemm_f16_kernel<0><<<dim3(8, NM / BM), 128, gemm_smem>>>(
        ct, w16 + 3 * WSZ, out, nullptr, nullptr, nullptr, nullptr, nullptr);
}

// round 15
// speedup vs baseline: 1.4419x; 1.4419x over previous
#include <cuda_runtime.h>
#include <cuda_bf16.h>
#include <cuda_fp16.h>
#include <math.h>

#define NB   2
#define NS   2048
#define NDM  1024
#define NH   16
#define NDK  64
#define NM   (NB * NS)   // 4096 rows
#define ASZ  ((size_t)NM * NDM)
#define WSZ  ((size_t)NDM * NDM)

// log2(e)/8: folds 1/sqrt(64) attention scale AND exp->ex2 (applied to K)
#define QSCALE 0.18033688011111366f

// Scratch (allocation-free rule: __device__ globals)
__device__ __align__(16) __half g_xs[ASZ];        // hidden states fp16 single
__device__ __align__(16) __half g_w16[4 * WSZ];   // Wq,Wk,Wv,Wo fp16
__device__ __align__(16) __half g_qs[ASZ];        // Q post-rope single fp16
__device__ __align__(16) __half g_kvv[2 * ASZ];   // [K(post-rope,scaled) | V]
__device__ __align__(16) __half g_ct[ASZ];        // ctx single fp16
__device__ __align__(16) float2 g_cs[(size_t)NM * 32];  // rope (cos,sin) table

// ---------------------------------------------------------------------------
// helpers
// ---------------------------------------------------------------------------
__device__ __forceinline__ void ldsm4(unsigned addr, unsigned& r0, unsigned& r1,
                                      unsigned& r2, unsigned& r3)
{
    asm volatile("ldmatrix.sync.aligned.m8n8.x4.shared.b16 {%0,%1,%2,%3}, [%4];"
                 : "=r"(r0), "=r"(r1), "=r"(r2), "=r"(r3) : "r"(addr));
}
__device__ __forceinline__ void ldsm4t(unsigned addr, unsigned& r0, unsigned& r1,
                                       unsigned& r2, unsigned& r3)
{
    asm volatile("ldmatrix.sync.aligned.m8n8.x4.trans.shared.b16 {%0,%1,%2,%3}, [%4];"
                 : "=r"(r0), "=r"(r1), "=r"(r2), "=r"(r3) : "r"(addr));
}
__device__ __forceinline__ void mma_f16(float* d, unsigned a0, unsigned a1,
                                        unsigned a2, unsigned a3,
                                        unsigned b0, unsigned b1)
{
    asm volatile("mma.sync.aligned.m16n8k16.row.col.f32.f16.f16.f32 "
                 "{%0,%1,%2,%3}, {%4,%5,%6,%7}, {%8,%9}, {%0,%1,%2,%3};"
                 : "+f"(d[0]), "+f"(d[1]), "+f"(d[2]), "+f"(d[3])
                 : "r"(a0), "r"(a1), "r"(a2), "r"(a3), "r"(b0), "r"(b1));
}
__device__ __forceinline__ unsigned packhf2(float e0, float e1)
{
    __half2 h = __floats2half2_rn(e0, e1);
    return *reinterpret_cast<unsigned*>(&h);
}
__device__ __forceinline__ unsigned h2exp2u(unsigned x)
{
    unsigned r;
    asm("ex2.approx.f16x2 %0, %1;" : "=r"(r) : "r"(x));
    return r;
}

// ---------------------------------------------------------------------------
// prep: [0..4095] hidden fp32->fp16, [4096..8191] weights fp32->fp16,
//       [8192..8703] rope cos/sin table (pos x 32 freqs)
// ---------------------------------------------------------------------------
__global__ __launch_bounds__(256) void prep_kernel(
    const float* __restrict__ hs, const int* __restrict__ pos,
    const float* __restrict__ w0, const float* __restrict__ w1,
    const float* __restrict__ w2, const float* __restrict__ w3,
    __half* __restrict__ xs, __half* __restrict__ w16)
{
    int b = blockIdx.x;
    if (b < 8192) {
        const float* src;
        __half* dst;
        int loc;
        if (b < 4096) {
            loc = b * 256 + threadIdx.x;
            src = hs; dst = xs;
        } else {
            int i = (b - 4096) * 256 + threadIdx.x;
            int widx = i >> 18;
            loc  = i & ((1 << 18) - 1);
            src = (widx == 0) ? w0 : (widx == 1) ? w1 : (widx == 2) ? w2 : w3;
            dst = w16 + (size_t)widx * WSZ;
        }
        float4 v = reinterpret_cast<const float4*>(src)[loc];
        __half2 h0 = __floats2half2_rn(v.x, v.y);
        __half2 h1 = __floats2half2_rn(v.z, v.w);
        reinterpret_cast<uint2*>(dst)[loc] = make_uint2(*(unsigned*)&h0, *(unsigned*)&h1);
    } else {
        int idx = (b - 8192) * 256 + threadIdx.x;   // [0, 4096*32)
        int m = idx >> 5, i = idx & 31;
        float p = (float)pos[m];
        float freq = (float)exp(-(double)(2 * i) / 64.0 * 9.210340371976184);
        float s, c;
        sincosf(p * freq, &s, &c);
        g_cs[idx] = make_float2(c, s);
    }
}

// ---------------------------------------------------------------------------
// Tensor-core GEMM: Y = A[M,K] * B[N,K]^T, fp16 1-MMA, BK=64 (16 iterations).
// 128B rows with XOR-16B swizzle (conflict-free ldsm, no padding).
// 128-thread CTA, block 128x128, 4 warps (2x2, 64x64 tiles), 3-stage cp.async.
// QKV=1: grid (24,32); widx: 0 -> Q (rope, ->g_qs), 1 -> K (rope*QSCALE,
//        ->g_kvv), 2 -> V (->g_kvv+ASZ).   QKV=0: grid (8,32); f32 out (Wo).
// ---------------------------------------------------------------------------
#define GBK      64
#define G_ROW_B  128                       // bytes per row (64 halfs)
#define G_B_OFF  16384                     // B region after 128 A rows
#define G_STG_B  32768                     // stage bytes
#define G_NSTG   3

template <int QKV>
__global__ __launch_bounds__(128, 2) void gemm_f16_kernel(
    const __half* __restrict__ A, const __half* __restrict__ Bbase,
    float* __restrict__ Y,
    __half* __restrict__ qs, __half* __restrict__ kvs, __half* __restrict__ v16,
    const int* __restrict__ pos)
{
    const int K = NDM, N = NDM;
    extern __shared__ __align__(16) __half smem[];

    int t = threadIdx.x;
    int warp = t >> 5, lane = t & 31;
    int wm = warp >> 1, wn = warp & 1;      // 2 x 2 warp grid (64x64 tiles)
    int widx = QKV ? (blockIdx.x >> 3) : 0;
    int nblk = QKV ? (blockIdx.x & 7) : blockIdx.x;
    int m0 = blockIdx.y * 128;
    int n0 = nblk * 128;
    const __half* B = Bbase + (size_t)widx * WSZ;

    unsigned smem_base = (unsigned)__cvta_generic_to_shared(smem);

    // 16 x 16B cp.async chunks per thread per stage (A 128 rows, B 128 rows)
    const __half* gsrc[16];
    unsigned sdst[16];
#pragma unroll
    for (int j = 0; j < 16; j++) {
        int g = t + j * 128;                // 0..2047
        int arr = g >> 10;                  // 0=A 1=B
        int rc  = g & 1023;
        int row = rc >> 3, c = rc & 7;
        const __half* base = arr ? B : A;
        int rg = (arr ? n0 : m0) + row;
        gsrc[j] = base + (size_t)rg * K + c * 8;
        sdst[j] = smem_base + (unsigned)(arr * G_B_OFF + row * G_ROW_B
                                         + ((c ^ (row & 7)) * 16));
    }

    float acc[4][8][4];
#pragma unroll
    for (int mt = 0; mt < 4; mt++)
#pragma unroll
        for (int nt = 0; nt < 8; nt++)
#pragma unroll
            for (int r = 0; r < 4; r++) acc[mt][nt][r] = 0.f;

    // prologue: stages 0 and 1
#pragma unroll
    for (int st = 0; st < G_NSTG - 1; st++) {
        unsigned soff = (unsigned)(st * G_STG_B);
        int koff = st * GBK;
#pragma unroll
        for (int j = 0; j < 16; j++)
            asm volatile("cp.async.cg.shared.global [%0], [%1], 16;"
                         :: "r"(sdst[j] + soff), "l"(gsrc[j] + koff));
        asm volatile("cp.async.commit_group;");
    }

    const int NI = K / GBK;   // 16
    int cur = 0;
    for (int it = 0; it < NI; it++) {
        if (it + 1 < NI) asm volatile("cp.async.wait_group 1;");
        else             asm volatile("cp.async.wait_group 0;");
        __syncthreads();

        if (it + 2 < NI) {
            int pf = cur + 2; if (pf >= G_NSTG) pf -= G_NSTG;
            unsigned soff = (unsigned)(pf * G_STG_B);
            int koff = (it + 2) * GBK;
#pragma unroll
            for (int j = 0; j < 16; j++)
                asm volatile("cp.async.cg.shared.global [%0], [%1], 16;"
                             :: "r"(sdst[j] + soff), "l"(gsrc[j] + koff));
            asm volatile("cp.async.commit_group;");
        }

        unsigned sb = smem_base + (unsigned)(cur * G_STG_B);
        int lrow = lane & 15;
        int khi  = (lane & 16) ? 8 : 0;

#pragma unroll
        for (int ks = 0; ks < 4; ks++) {
            int kof = ks * 16 + khi;        // halfs; 16B chunk = kof>>3
            unsigned bh[8][2];
#pragma unroll
            for (int bn = 0; bn < 4; bn++) {
                int nrow = wn * 64 + bn * 16 + lrow;
                unsigned addr = sb + (unsigned)(G_B_OFF + nrow * G_ROW_B
                                    + (((kof >> 3) ^ (nrow & 7)) * 16));
                unsigned r0, r1, r2, r3;
                ldsm4(addr, r0, r1, r2, r3);
                bh[bn * 2][0] = r0; bh[bn * 2 + 1][0] = r1;
                bh[bn * 2][1] = r2; bh[bn * 2 + 1][1] = r3;
            }
#pragma unroll
            for (int mt = 0; mt < 4; mt++) {
                int mrow = wm * 64 + mt * 16 + lrow;
                unsigned addr = sb + (unsigned)(mrow * G_ROW_B
                                    + (((kof >> 3) ^ (mrow & 7)) * 16));
                unsigned a0, a1, a2, a3;
                ldsm4(addr, a0, a1, a2, a3);
#pragma unroll
                for (int nt = 0; nt < 8; nt++)
                    mma_f16(acc[mt][nt], a0, a1, a2, a3, bh[nt][0], bh[nt][1]);
            }
        }
        cur++; if (cur == G_NSTG) cur = 0;
    }

    // ---- epilogue ----
#pragma unroll
    for (int mt = 0; mt < 4; mt++) {
        int r = m0 + wm * 64 + mt * 16 + (lane >> 2);
#pragma unroll
        for (int half = 0; half < 2; half++) {
            int gr = r + half * 8;          // global row (b*S + s)
            if (QKV == 0) {
#pragma unroll
                for (int nt = 0; nt < 8; nt++) {
                    int cc = n0 + wn * 64 + nt * 8 + (lane & 3) * 2;
                    size_t idx = (size_t)gr * N + cc;
                    *reinterpret_cast<float2*>(&Y[idx]) =
                        make_float2(acc[mt][nt][half * 2], acc[mt][nt][half * 2 + 1]);
                }
            } else if (widx == 2) {
#pragma unroll
                for (int nt = 0; nt < 8; nt++) {
                    int cc = n0 + wn * 64 + nt * 8 + (lane & 3) * 2;
                    size_t idx = (size_t)gr * N + cc;
                    __half2 h2 = __floats2half2_rn(acc[mt][nt][half * 2],
                                                   acc[mt][nt][half * 2 + 1]);
                    *reinterpret_cast<__half2*>(v16 + idx) = h2;
                }
            } else {
                // RoPE: pair (nt, nt+4) = head-local cols (i, i+32)
#pragma unroll
                for (int nt = 0; nt < 4; nt++) {
                    int hl = nt * 8 + (lane & 3) * 2;       // head-local i, i+1
                    float r1[2], r2[2];
#pragma unroll
                    for (int jj = 0; jj < 2; jj++) {
                        float2 cs = g_cs[(size_t)gr * 32 + hl + jj];
                        float x1 = acc[mt][nt][half * 2 + jj];
                        float x2 = acc[mt][nt + 4][half * 2 + jj];
                        r1[jj] = x1 * cs.x - x2 * cs.y;
                        r2[jj] = x2 * cs.x + x1 * cs.y;
                    }
                    int cc = n0 + wn * 64 + nt * 8 + (lane & 3) * 2;
                    size_t idx = (size_t)gr * N + cc;
                    if (widx == 0) {
                        *reinterpret_cast<__half2*>(qs + idx) =
                            __floats2half2_rn(r1[0], r1[1]);
                        *reinterpret_cast<__half2*>(qs + idx + 32) =
                            __floats2half2_rn(r2[0], r2[1]);
                    } else {
                        *reinterpret_cast<__half2*>(kvs + idx) =
                            __floats2half2_rn(r1[0] * QSCALE, r1[1] * QSCALE);
                        *reinterpret_cast<__half2*>(kvs + idx + 32) =
                            __floats2half2_rn(r2[0] * QSCALE, r2[1] * QSCALE);
                    }
                }
            }
        }
    }
    (void)pos;
}

// ---------------------------------------------------------------------------
// Tensor-core flash attention, fp16, max-free softmax, 32 q-rows per warp.
// QK -> exp -> PV interleaved per 16-key block. 128 threads, 3 CTAs/SM.
// (unchanged from R12/R14)
// ---------------------------------------------------------------------------
#define AP 72
#define AT_STAGE_E (2 * 64 * AP)
#define AT_STAGE_B (AT_STAGE_E * 2)       // 18432 B
#define K_OFF 0
#define V_OFF (64 * AP)
#define ONES2 0x3C003C00u                 // half2 (1.0, 1.0)

__global__ __launch_bounds__(128, 3) void attn_tc_kernel()
{
    extern __shared__ __align__(16) __half att_smem[];
    unsigned sbase = (unsigned)__cvta_generic_to_shared(att_smem);

    int t = threadIdx.x, lane = t & 31, warp = t >> 5;
    int qt = blockIdx.x, h = blockIdx.y, b = blockIdx.z;
    int g = lane >> 2, qr = lane & 3;

    unsigned aQ[2][4][4];
    size_t qbase[2];
#pragma unroll
    for (int mh = 0; mh < 2; mh++) {
        size_t qrow0 = (size_t)(b * NS + qt * 128 + warp * 32 + mh * 16 + g) * NDM
                     + (size_t)h * NDK;
        size_t qrow8 = qrow0 + 8 * NDM;
        qbase[mh] = qrow0;
#pragma unroll
        for (int kk = 0; kk < 4; kk++) {
            int kc = kk * 16 + qr * 2;
            aQ[mh][kk][0] = *reinterpret_cast<const unsigned*>(g_qs + qrow0 + kc);
            aQ[mh][kk][1] = *reinterpret_cast<const unsigned*>(g_qs + qrow8 + kc);
            aQ[mh][kk][2] = *reinterpret_cast<const unsigned*>(g_qs + qrow0 + kc + 8);
            aQ[mh][kk][3] = *reinterpret_cast<const unsigned*>(g_qs + qrow8 + kc + 8);
        }
    }

    const __half* gbase = g_kvv + (size_t)(b * NS) * NDM + (size_t)h * NDK;
    unsigned goffs[8];
    unsigned sdst[8];
#pragma unroll
    for (int i = 0; i < 8; i++) {
        int gi = t + i * 128;
        int arr = gi >> 9;            // 0=K 1=V
        int rw  = (gi & 511) >> 3;    // key row 0..63
        int c   = gi & 7;             // 16B chunk in 128B row
        goffs[i] = (unsigned)(arr * ASZ + (size_t)rw * NDM + c * 8);
        sdst[i] = sbase + (unsigned)((arr * 64 * AP + rw * AP + c * 8) * 2);
    }

    float o[2][8][4];
#pragma unroll
    for (int mh = 0; mh < 2; mh++)
#pragma unroll
        for (int j = 0; j < 8; j++)
#pragma unroll
            for (int r = 0; r < 4; r++) o[mh][j][r] = 0.f;
    float osum[2][4] = {{0.f, 0.f, 0.f, 0.f}, {0.f, 0.f, 0.f, 0.f}};

#pragma unroll
    for (int st = 0; st < 2; st++) {
        unsigned soff = (unsigned)(st * AT_STAGE_B);
        unsigned goff = (unsigned)(st * 64 * NDM);
#pragma unroll
        for (int i = 0; i < 8; i++)
            asm volatile("cp.async.cg.shared.global [%0], [%1], 16;"
                         :: "r"(sdst[i] + soff), "l"(gbase + goffs[i] + goff));
        asm volatile("cp.async.commit_group;");
    }

    const int NT = NS / 64;  // 32
    int cur = 0;
    for (int kt = 0; kt < NT; kt++) {
        if (kt + 1 < NT) asm volatile("cp.async.wait_group 1;");
        else             asm volatile("cp.async.wait_group 0;");
        __syncthreads();

        if (kt + 2 < NT) {
            int pf = cur + 2; if (pf >= 3) pf -= 3;
            unsigned soff = (unsigned)(pf * AT_STAGE_B);
            unsigned goff = (unsigned)((kt + 2) * 64 * NDM);
#pragma unroll
            for (int i = 0; i < 8; i++)
                asm volatile("cp.async.cg.shared.global [%0], [%1], 16;"
                             :: "r"(sdst[i] + soff), "l"(gbase + goffs[i] + goff));
            asm volatile("cp.async.commit_group;");
        }

        unsigned sb = sbase + (unsigned)(cur * AT_STAGE_B);
        int lr15 = lane & 15;
        int khi  = (lane & 16) ? 8 : 0;

#pragma unroll
        for (int u = 0; u < 4; u++) {
            float s0[4] = {0.f, 0.f, 0.f, 0.f};
            float s1[4] = {0.f, 0.f, 0.f, 0.f};
            float s2[4] = {0.f, 0.f, 0.f, 0.f};
            float s3[4] = {0.f, 0.f, 0.f, 0.f};
#pragma unroll
            for (int kk = 0; kk < 4; kk++) {
                unsigned addr = sb + (unsigned)((K_OFF + (u * 16 + lr15) * AP
                                                + kk * 16 + khi) * 2);
                unsigned k0, k1, k2, k3;
                ldsm4(addr, k0, k1, k2, k3);
                mma_f16(s0, aQ[0][kk][0], aQ[0][kk][1], aQ[0][kk][2], aQ[0][kk][3], k0, k2);
                mma_f16(s1, aQ[0][kk][0], aQ[0][kk][1], aQ[0][kk][2], aQ[0][kk][3], k1, k3);
                mma_f16(s2, aQ[1][kk][0], aQ[1][kk][1], aQ[1][kk][2], aQ[1][kk][3], k0, k2);
                mma_f16(s3, aQ[1][kk][0], aQ[1][kk][1], aQ[1][kk][2], aQ[1][kk][3], k1, k3);
            }

            unsigned ph0[4], ph1[4];
            ph0[0] = h2exp2u(packhf2(s0[0], s0[1]));
            ph0[1] = h2exp2u(packhf2(s0[2], s0[3]));
            ph0[2] = h2exp2u(packhf2(s1[0], s1[1]));
            ph0[3] = h2exp2u(packhf2(s1[2], s1[3]));
            ph1[0] = h2exp2u(packhf2(s2[0], s2[1]));
            ph1[1] = h2exp2u(packhf2(s2[2], s2[3]));
            ph1[2] = h2exp2u(packhf2(s3[0], s3[1]));
            ph1[3] = h2exp2u(packhf2(s3[2], s3[3]));

            mma_f16(osum[0], ph0[0], ph0[1], ph0[2], ph0[3], ONES2, ONES2);
            mma_f16(osum[1], ph1[0], ph1[1], ph1[2], ph1[3], ONES2, ONES2);

#pragma unroll
            for (int n0 = 0; n0 < 64; n0 += 16) {
                unsigned addr = sb + (unsigned)((V_OFF + (u * 16 + lr15) * AP
                                                + n0 + ((lane >> 4) & 1) * 8) * 2);
                unsigned v0, v1, v2, v3;
                ldsm4t(addr, v0, v1, v2, v3);
                int j = n0 >> 3;
                mma_f16(o[0][j],   ph0[0], ph0[1], ph0[2], ph0[3], v0, v1);
                mma_f16(o[0][j+1], ph0[0], ph0[1], ph0[2], ph0[3], v2, v3);
                mma_f16(o[1][j],   ph1[0], ph1[1], ph1[2], ph1[3], v0, v1);
                mma_f16(o[1][j+1], ph1[0], ph1[1], ph1[2], ph1[3], v2, v3);
            }
        }
        cur++; if (cur == 3) cur = 0;
    }

#pragma unroll
    for (int mh = 0; mh < 2; mh++) {
        float inv0 = 1.f / osum[mh][0], inv1 = 1.f / osum[mh][2];
        size_t orow0 = qbase[mh];
        size_t orow8 = orow0 + 8 * NDM;
#pragma unroll
        for (int j = 0; j < 8; j++) {
            int cc = j * 8 + qr * 2;
            __half2 h0 = __floats2half2_rn(o[mh][j][0] * inv0, o[mh][j][1] * inv0);
            __half2 h1 = __floats2half2_rn(o[mh][j][2] * inv1, o[mh][j][3] * inv1);
            *reinterpret_cast<__half2*>(g_ct + orow0 + cc) = h0;
            *reinterpret_cast<__half2*>(g_ct + orow8 + cc) = h1;
        }
    }
}

// ---------------------------------------------------------------------------
extern "C" void kernel_launch(void* const* d_in, const int* in_sizes, int n_in,
                              void* d_out, int out_size)
{
    const float* hs  = (const float*)d_in[0];
    const int*   pos = (const int*)  d_in[1];
    const float* Wq  = (const float*)d_in[2];
    const float* Wk  = (const float*)d_in[3];
    const float* Wv  = (const float*)d_in[4];
    const float* Wo  = (const float*)d_in[5];
    float* out = (float*)d_out;
    (void)in_sizes; (void)n_in; (void)out_size;

    __half *xs, *w16, *qs, *kvv, *ct;
    cudaGetSymbolAddress((void**)&xs,  g_xs);
    cudaGetSymbolAddress((void**)&w16, g_w16);
    cudaGetSymbolAddress((void**)&qs,  g_qs);
    cudaGetSymbolAddress((void**)&kvv, g_kvv);
    cudaGetSymbolAddress((void**)&ct,  g_ct);

    int gemm_smem = G_NSTG * G_STG_B;   // 98304 B
    cudaFuncSetAttribute(gemm_f16_kernel<1>,
                         cudaFuncAttributeMaxDynamicSharedMemorySize, gemm_smem);
    cudaFuncSetAttribute(gemm_f16_kernel<0>,
                         cudaFuncAttributeMaxDynamicSharedMemorySize, gemm_smem);

    // [0] prep: hidden + weights + rope table
    prep_kernel<<<8704, 256>>>(hs, pos, Wq, Wk, Wv, Wo, xs, w16);

    // [1] fused QKV projection with RoPE epilogue (BK=64)
    gemm_f16_kernel<1><<<dim3(24, NM / 128), 128, gemm_smem>>>(
        xs, w16, nullptr, qs, kvv, kvv + ASZ, pos);

    // [2] attention
    int attn_smem = 3 * AT_STAGE_B;   // 55296 B
    cudaFuncSetAttribute(attn_tc_kernel,
                         cudaFuncAttributeMaxDynamicSharedMemorySize, attn_smem);
    attn_tc_kernel<<<dim3(NS / 128, NH, NB), 128, attn_smem>>>();

    // [3] output projection (BK=64)
    gemm_f16_kernel<0><<<dim3(8, NM / 128), 128, gemm_smem>>>(
        ct, w16 + 3 * WSZ, out, nullptr, nullptr, nullptr, pos);
}

// round 16
// speedup vs baseline: 1.4609x; 1.0132x over previous
#include <cuda_runtime.h>
#include <cuda_bf16.h>
#include <cuda_fp16.h>
#include <math.h>

#define NB   2
#define NS   2048
#define NDM  1024
#define NH   16
#define NDK  64
#define NM   (NB * NS)   // 4096 rows
#define ASZ  ((size_t)NM * NDM)
#define WSZ  ((size_t)NDM * NDM)

// log2(e)/8: folds 1/sqrt(64) attention scale AND exp->ex2 (applied to K)
#define QSCALE 0.18033688011111366f

// Scratch (allocation-free rule: __device__ globals)
__device__ __align__(16) __half g_xs[ASZ];        // hidden states fp16 single
__device__ __align__(16) __half g_w16[4 * WSZ];   // Wq,Wk,Wv,Wo fp16
__device__ __align__(16) __half g_qs[ASZ];        // Q post-rope single fp16
__device__ __align__(16) __half g_kvv[2 * ASZ];   // [K(post-rope,scaled) | V]
__device__ __align__(16) __half g_ct[ASZ];        // ctx single fp16
__device__ __align__(16) float2 g_cs[(size_t)NM * 32];  // rope (cos,sin) table

// ---------------------------------------------------------------------------
// helpers
// ---------------------------------------------------------------------------
__device__ __forceinline__ void ldsm4(unsigned addr, unsigned& r0, unsigned& r1,
                                      unsigned& r2, unsigned& r3)
{
    asm volatile("ldmatrix.sync.aligned.m8n8.x4.shared.b16 {%0,%1,%2,%3}, [%4];"
                 : "=r"(r0), "=r"(r1), "=r"(r2), "=r"(r3) : "r"(addr));
}
__device__ __forceinline__ void ldsm4t(unsigned addr, unsigned& r0, unsigned& r1,
                                       unsigned& r2, unsigned& r3)
{
    asm volatile("ldmatrix.sync.aligned.m8n8.x4.trans.shared.b16 {%0,%1,%2,%3}, [%4];"
                 : "=r"(r0), "=r"(r1), "=r"(r2), "=r"(r3) : "r"(addr));
}
__device__ __forceinline__ void mma_f16(float* d, unsigned a0, unsigned a1,
                                        unsigned a2, unsigned a3,
                                        unsigned b0, unsigned b1)
{
    asm volatile("mma.sync.aligned.m16n8k16.row.col.f32.f16.f16.f32 "
                 "{%0,%1,%2,%3}, {%4,%5,%6,%7}, {%8,%9}, {%0,%1,%2,%3};"
                 : "+f"(d[0]), "+f"(d[1]), "+f"(d[2]), "+f"(d[3])
                 : "r"(a0), "r"(a1), "r"(a2), "r"(a3), "r"(b0), "r"(b1));
}
__device__ __forceinline__ unsigned packhf2(float e0, float e1)
{
    __half2 h = __floats2half2_rn(e0, e1);
    return *reinterpret_cast<unsigned*>(&h);
}
__device__ __forceinline__ unsigned h2exp2u(unsigned x)
{
    unsigned r;
    asm("ex2.approx.f16x2 %0, %1;" : "=r"(r) : "r"(x));
    return r;
}

// ---------------------------------------------------------------------------
// prep: [0..4095] hidden fp32->fp16, [4096..8191] weights fp32->fp16,
//       [8192..8703] rope cos/sin table (pos x 32 freqs)
// ---------------------------------------------------------------------------
__global__ __launch_bounds__(256) void prep_kernel(
    const float* __restrict__ hs, const int* __restrict__ pos,
    const float* __restrict__ w0, const float* __restrict__ w1,
    const float* __restrict__ w2, const float* __restrict__ w3,
    __half* __restrict__ xs, __half* __restrict__ w16)
{
    int b = blockIdx.x;
    if (b < 8192) {
        const float* src;
        __half* dst;
        int loc;
        if (b < 4096) {
            loc = b * 256 + threadIdx.x;
            src = hs; dst = xs;
        } else {
            int i = (b - 4096) * 256 + threadIdx.x;
            int widx = i >> 18;
            loc  = i & ((1 << 18) - 1);
            src = (widx == 0) ? w0 : (widx == 1) ? w1 : (widx == 2) ? w2 : w3;
            dst = w16 + (size_t)widx * WSZ;
        }
        float4 v = reinterpret_cast<const float4*>(src)[loc];
        __half2 h0 = __floats2half2_rn(v.x, v.y);
        __half2 h1 = __floats2half2_rn(v.z, v.w);
        reinterpret_cast<uint2*>(dst)[loc] = make_uint2(*(unsigned*)&h0, *(unsigned*)&h1);
    } else {
        int idx = (b - 8192) * 256 + threadIdx.x;   // [0, 4096*32)
        int m = idx >> 5, i = idx & 31;
        float p = (float)pos[m];
        float freq = (float)exp(-(double)(2 * i) / 64.0 * 9.210340371976184);
        float s, c;
        sincosf(p * freq, &s, &c);
        g_cs[idx] = make_float2(c, s);
    }
}

// ---------------------------------------------------------------------------
// Tensor-core GEMM: Y = A[M,K] * B[N,K]^T, fp16 1-MMA, BK=64 (16 iterations).
// 2-stage cp.async ring (64 KB smem), slim addressing, 3 CTAs/SM target.
// QKV=1: grid (24,32); widx: 0 -> Q (rope, ->g_qs), 1 -> K (rope*QSCALE,
//        ->g_kvv), 2 -> V (->g_kvv+ASZ).   QKV=0: grid (8,32); f32 out (Wo).
// ---------------------------------------------------------------------------
#define GBK      64
#define G_ROW_B  128                       // bytes per row (64 halfs)
#define G_B_OFF  16384                     // B region after 128 A rows
#define G_STG_B  32768                     // stage bytes
#define G_NSTG   2

template <int QKV>
__global__ __launch_bounds__(128, 3) void gemm_f16_kernel(
    const __half* __restrict__ A, const __half* __restrict__ Bbase,
    float* __restrict__ Y,
    __half* __restrict__ qs, __half* __restrict__ kvs, __half* __restrict__ v16)
{
    const int K = NDM, N = NDM;
    extern __shared__ __align__(16) __half smem[];

    int t = threadIdx.x;
    int warp = t >> 5, lane = t & 31;
    int wm = warp >> 1, wn = warp & 1;      // 2 x 2 warp grid (64x64 tiles)
    int widx = QKV ? (blockIdx.x >> 3) : 0;
    int nblk = QKV ? (blockIdx.x & 7) : blockIdx.x;
    int m0 = blockIdx.y * 128;
    int n0 = nblk * 128;
    const __half* B = Bbase + (size_t)widx * WSZ;

    unsigned smem_base = (unsigned)__cvta_generic_to_shared(smem);

    // slim cp.async addressing: 2 base pointers + linear strides
    int tr = t >> 3;                        // row base 0..15
    int tc = t & 7;                         // 16B chunk in 128B row
    const __half* gA = A + (size_t)(m0 + tr) * K + tc * 8;
    const __half* gB = B + (size_t)(n0 + tr) * K + tc * 8;
    unsigned sA0 = smem_base + (unsigned)(tr * G_ROW_B + ((tc ^ (tr & 7)) * 16));
    unsigned sB0 = sA0 + G_B_OFF;

#define G_LOAD(soff, koff)                                                    \
    {                                                                         \
        _Pragma("unroll")                                                     \
        for (int j = 0; j < 8; j++)                                           \
            asm volatile("cp.async.cg.shared.global [%0], [%1], 16;"         \
                         :: "r"(sA0 + (soff) + j * (16 * G_ROW_B)),           \
                            "l"(gA + (koff) + (size_t)j * 16 * K));           \
        _Pragma("unroll")                                                     \
        for (int j = 0; j < 8; j++)                                           \
            asm volatile("cp.async.cg.shared.global [%0], [%1], 16;"         \
                         :: "r"(sB0 + (soff) + j * (16 * G_ROW_B)),           \
                            "l"(gB + (koff) + (size_t)j * 16 * K));           \
        asm volatile("cp.async.commit_group;");                               \
    }

    float acc[4][8][4];
#pragma unroll
    for (int mt = 0; mt < 4; mt++)
#pragma unroll
        for (int nt = 0; nt < 8; nt++)
#pragma unroll
            for (int r = 0; r < 4; r++) acc[mt][nt][r] = 0.f;

    // prologue: stage 0
    G_LOAD(0u, 0);

    const int NI = NDM / GBK;   // 16
    for (int it = 0; it < NI; it++) {
        asm volatile("cp.async.wait_group 0;");
        __syncthreads();        // stage it resident; prev compute done everywhere

        if (it + 1 < NI)
            G_LOAD((unsigned)(((it + 1) & 1) * G_STG_B), (it + 1) * GBK);

        unsigned sb = smem_base + (unsigned)((it & 1) * G_STG_B);
        int lrow = lane & 15;
        int khi  = (lane & 16) ? 8 : 0;

#pragma unroll
        for (int ks = 0; ks < 4; ks++) {
            int kc16 = ((ks * 16 + khi) >> 3);       // 16B chunk index 0..7
            unsigned bh[8][2];
#pragma unroll
            for (int bn = 0; bn < 4; bn++) {
                int nrow = wn * 64 + bn * 16 + lrow;
                unsigned addr = sb + (unsigned)(G_B_OFF + nrow * G_ROW_B
                                    + ((kc16 ^ (nrow & 7)) * 16));
                unsigned r0, r1, r2, r3;
                ldsm4(addr, r0, r1, r2, r3);
                bh[bn * 2][0] = r0; bh[bn * 2 + 1][0] = r1;
                bh[bn * 2][1] = r2; bh[bn * 2 + 1][1] = r3;
            }
#pragma unroll
            for (int mt = 0; mt < 4; mt++) {
                int mrow = wm * 64 + mt * 16 + lrow;
                unsigned addr = sb + (unsigned)(mrow * G_ROW_B
                                    + ((kc16 ^ (mrow & 7)) * 16));
                unsigned a0, a1, a2, a3;
                ldsm4(addr, a0, a1, a2, a3);
#pragma unroll
                for (int nt = 0; nt < 8; nt++)
                    mma_f16(acc[mt][nt], a0, a1, a2, a3, bh[nt][0], bh[nt][1]);
            }
        }
    }
#undef G_LOAD

    // ---- epilogue ----
#pragma unroll
    for (int mt = 0; mt < 4; mt++) {
        int r = m0 + wm * 64 + mt * 16 + (lane >> 2);
#pragma unroll
        for (int half = 0; half < 2; half++) {
            int gr = r + half * 8;          // global row (b*S + s)
            if (QKV == 0) {
#pragma unroll
                for (int nt = 0; nt < 8; nt++) {
                    int cc = n0 + wn * 64 + nt * 8 + (lane & 3) * 2;
                    size_t idx = (size_t)gr * N + cc;
                    *reinterpret_cast<float2*>(&Y[idx]) =
                        make_float2(acc[mt][nt][half * 2], acc[mt][nt][half * 2 + 1]);
                }
            } else if (widx == 2) {
#pragma unroll
                for (int nt = 0; nt < 8; nt++) {
                    int cc = n0 + wn * 64 + nt * 8 + (lane & 3) * 2;
                    size_t idx = (size_t)gr * N + cc;
                    __half2 h2 = __floats2half2_rn(acc[mt][nt][half * 2],
                                                   acc[mt][nt][half * 2 + 1]);
                    *reinterpret_cast<__half2*>(v16 + idx) = h2;
                }
            } else {
                // RoPE: pair (nt, nt+4) = head-local cols (i, i+32)
#pragma unroll
                for (int nt = 0; nt < 4; nt++) {
                    int hl = nt * 8 + (lane & 3) * 2;       // head-local i, i+1
                    float r1[2], r2[2];
#pragma unroll
                    for (int jj = 0; jj < 2; jj++) {
                        float2 cs = g_cs[(size_t)gr * 32 + hl + jj];
                        float x1 = acc[mt][nt][half * 2 + jj];
                        float x2 = acc[mt][nt + 4][half * 2 + jj];
                        r1[jj] = x1 * cs.x - x2 * cs.y;
                        r2[jj] = x2 * cs.x + x1 * cs.y;
                    }
                    int cc = n0 + wn * 64 + nt * 8 + (lane & 3) * 2;
                    size_t idx = (size_t)gr * N + cc;
                    if (widx == 0) {
                        *reinterpret_cast<__half2*>(qs + idx) =
                            __floats2half2_rn(r1[0], r1[1]);
                        *reinterpret_cast<__half2*>(qs + idx + 32) =
                            __floats2half2_rn(r2[0], r2[1]);
                    } else {
                        *reinterpret_cast<__half2*>(kvs + idx) =
                            __floats2half2_rn(r1[0] * QSCALE, r1[1] * QSCALE);
                        *reinterpret_cast<__half2*>(kvs + idx + 32) =
                            __floats2half2_rn(r2[0] * QSCALE, r2[1] * QSCALE);
                    }
                }
            }
        }
    }
}

// ---------------------------------------------------------------------------
// Tensor-core flash attention, fp16, max-free softmax, 32 q-rows per warp.
// PERSISTENT: grid 444 (=148*3, one full wave at 3 CTAs/SM); CTA processes
// items bid, bid+444 of the 512 (qt, h, b) work items -> the 68 double-item
// CTAs land on distinct SMs (kills the 2-wave quantization at grid 512).
// ---------------------------------------------------------------------------
#define AP 72
#define AT_STAGE_E (2 * 64 * AP)
#define AT_STAGE_B (AT_STAGE_E * 2)       // 18432 B
#define K_OFF 0
#define V_OFF (64 * AP)
#define ONES2 0x3C003C00u                 // half2 (1.0, 1.0)
#define AT_GRID 444
#define AT_ITEMS 512                      // 16 qt x 16 h x 2 b

__global__ __launch_bounds__(128, 3) void attn_tc_kernel()
{
    extern __shared__ __align__(16) __half att_smem[];
    unsigned sbase = (unsigned)__cvta_generic_to_shared(att_smem);

    int t = threadIdx.x, lane = t & 31, warp = t >> 5;
    int g = lane >> 2, qr = lane & 3;

    // item-independent smem cp.async destinations + kv offsets
    unsigned goffs[8];
    unsigned sdst[8];
#pragma unroll
    for (int i = 0; i < 8; i++) {
        int gi = t + i * 128;
        int arr = gi >> 9;            // 0=K 1=V
        int rw  = (gi & 511) >> 3;    // key row 0..63
        int c   = gi & 7;             // 16B chunk in 128B row
        goffs[i] = (unsigned)(arr * ASZ + (size_t)rw * NDM + c * 8);
        sdst[i] = sbase + (unsigned)((arr * 64 * AP + rw * AP + c * 8) * 2);
    }

    for (int wi = blockIdx.x; wi < AT_ITEMS; wi += AT_GRID) {
        int qt = wi & 15;
        int h  = (wi >> 4) & 15;
        int b  = wi >> 8;

        // --- Q fragments for this warp's 32 rows (2 m16 halves) ---
        unsigned aQ[2][4][4];
        size_t qbase[2];
#pragma unroll
        for (int mh = 0; mh < 2; mh++) {
            size_t qrow0 = (size_t)(b * NS + qt * 128 + warp * 32 + mh * 16 + g) * NDM
                         + (size_t)h * NDK;
            size_t qrow8 = qrow0 + 8 * NDM;
            qbase[mh] = qrow0;
#pragma unroll
            for (int kk = 0; kk < 4; kk++) {
                int kc = kk * 16 + qr * 2;
                aQ[mh][kk][0] = *reinterpret_cast<const unsigned*>(g_qs + qrow0 + kc);
                aQ[mh][kk][1] = *reinterpret_cast<const unsigned*>(g_qs + qrow8 + kc);
                aQ[mh][kk][2] = *reinterpret_cast<const unsigned*>(g_qs + qrow0 + kc + 8);
                aQ[mh][kk][3] = *reinterpret_cast<const unsigned*>(g_qs + qrow8 + kc + 8);
            }
        }

        const __half* gbase = g_kvv + (size_t)(b * NS) * NDM + (size_t)h * NDK;

        float o[2][8][4];
#pragma unroll
        for (int mh = 0; mh < 2; mh++)
#pragma unroll
            for (int j = 0; j < 8; j++)
#pragma unroll
                for (int r = 0; r < 4; r++) o[mh][j][r] = 0.f;
        float osum[2][4] = {{0.f, 0.f, 0.f, 0.f}, {0.f, 0.f, 0.f, 0.f}};

        // prologue: stages 0 and 1
#pragma unroll
        for (int st = 0; st < 2; st++) {
            unsigned soff = (unsigned)(st * AT_STAGE_B);
            unsigned goff = (unsigned)(st * 64 * NDM);
#pragma unroll
            for (int i = 0; i < 8; i++)
                asm volatile("cp.async.cg.shared.global [%0], [%1], 16;"
                             :: "r"(sdst[i] + soff), "l"(gbase + goffs[i] + goff));
            asm volatile("cp.async.commit_group;");
        }

        const int NT = NS / 64;  // 32
        int cur = 0;
        for (int kt = 0; kt < NT; kt++) {
            if (kt + 1 < NT) asm volatile("cp.async.wait_group 1;");
            else             asm volatile("cp.async.wait_group 0;");
            __syncthreads();

            if (kt + 2 < NT) {
                int pf = cur + 2; if (pf >= 3) pf -= 3;
                unsigned soff = (unsigned)(pf * AT_STAGE_B);
                unsigned goff = (unsigned)((kt + 2) * 64 * NDM);
#pragma unroll
                for (int i = 0; i < 8; i++)
                    asm volatile("cp.async.cg.shared.global [%0], [%1], 16;"
                                 :: "r"(sdst[i] + soff), "l"(gbase + goffs[i] + goff));
                asm volatile("cp.async.commit_group;");
            }

            unsigned sb = sbase + (unsigned)(cur * AT_STAGE_B);
            int lr15 = lane & 15;
            int khi  = (lane & 16) ? 8 : 0;

#pragma unroll
            for (int u = 0; u < 4; u++) {
                float s0[4] = {0.f, 0.f, 0.f, 0.f};
                float s1[4] = {0.f, 0.f, 0.f, 0.f};
                float s2[4] = {0.f, 0.f, 0.f, 0.f};
                float s3[4] = {0.f, 0.f, 0.f, 0.f};
#pragma unroll
                for (int kk = 0; kk < 4; kk++) {
                    unsigned addr = sb + (unsigned)((K_OFF + (u * 16 + lr15) * AP
                                                    + kk * 16 + khi) * 2);
                    unsigned k0, k1, k2, k3;
                    ldsm4(addr, k0, k1, k2, k3);
                    mma_f16(s0, aQ[0][kk][0], aQ[0][kk][1], aQ[0][kk][2], aQ[0][kk][3], k0, k2);
                    mma_f16(s1, aQ[0][kk][0], aQ[0][kk][1], aQ[0][kk][2], aQ[0][kk][3], k1, k3);
                    mma_f16(s2, aQ[1][kk][0], aQ[1][kk][1], aQ[1][kk][2], aQ[1][kk][3], k0, k2);
                    mma_f16(s3, aQ[1][kk][0], aQ[1][kk][1], aQ[1][kk][2], aQ[1][kk][3], k1, k3);
                }

                unsigned ph0[4], ph1[4];
                ph0[0] = h2exp2u(packhf2(s0[0], s0[1]));
                ph0[1] = h2exp2u(packhf2(s0[2], s0[3]));
                ph0[2] = h2exp2u(packhf2(s1[0], s1[1]));
                ph0[3] = h2exp2u(packhf2(s1[2], s1[3]));
                ph1[0] = h2exp2u(packhf2(s2[0], s2[1]));
                ph1[1] = h2exp2u(packhf2(s2[2], s2[3]));
                ph1[2] = h2exp2u(packhf2(s3[0], s3[1]));
                ph1[3] = h2exp2u(packhf2(s3[2], s3[3]));

                mma_f16(osum[0], ph0[0], ph0[1], ph0[2], ph0[3], ONES2, ONES2);
                mma_f16(osum[1], ph1[0], ph1[1], ph1[2], ph1[3], ONES2, ONES2);

#pragma unroll
                for (int n0 = 0; n0 < 64; n0 += 16) {
                    unsigned addr = sb + (unsigned)((V_OFF + (u * 16 + lr15) * AP
                                                    + n0 + ((lane >> 4) & 1) * 8) * 2);
                    unsigned v0, v1, v2, v3;
                    ldsm4t(addr, v0, v1, v2, v3);
                    int j = n0 >> 3;
                    mma_f16(o[0][j],   ph0[0], ph0[1], ph0[2], ph0[3], v0, v1);
                    mma_f16(o[0][j+1], ph0[0], ph0[1], ph0[2], ph0[3], v2, v3);
                    mma_f16(o[1][j],   ph1[0], ph1[1], ph1[2], ph1[3], v0, v1);
                    mma_f16(o[1][j+1], ph1[0], ph1[1], ph1[2], ph1[3], v2, v3);
                }
            }
            cur++; if (cur == 3) cur = 0;
        }

        // ---- epilogue: osum[mh][0]/osum[mh][2] are exact row sums ----
#pragma unroll
        for (int mh = 0; mh < 2; mh++) {
            float inv0 = 1.f / osum[mh][0], inv1 = 1.f / osum[mh][2];
            size_t orow0 = qbase[mh];
            size_t orow8 = orow0 + 8 * NDM;
#pragma unroll
            for (int j = 0; j < 8; j++) {
                int cc = j * 8 + qr * 2;
                __half2 h0 = __floats2half2_rn(o[mh][j][0] * inv0, o[mh][j][1] * inv0);
                __half2 h1 = __floats2half2_rn(o[mh][j][2] * inv1, o[mh][j][3] * inv1);
                *reinterpret_cast<__half2*>(g_ct + orow0 + cc) = h0;
                *reinterpret_cast<__half2*>(g_ct + orow8 + cc) = h1;
            }
        }
        __syncthreads();   // all warps done with smem before next item's prologue
    }
}

// ---------------------------------------------------------------------------
extern "C" void kernel_launch(void* const* d_in, const int* in_sizes, int n_in,
                              void* d_out, int out_size)
{
    const float* hs  = (const float*)d_in[0];
    const int*   pos = (const int*)  d_in[1];
    const float* Wq  = (const float*)d_in[2];
    const float* Wk  = (const float*)d_in[3];
    const float* Wv  = (const float*)d_in[4];
    const float* Wo  = (const float*)d_in[5];
    float* out = (float*)d_out;
    (void)in_sizes; (void)n_in; (void)out_size;

    __half *xs, *w16, *qs, *kvv, *ct;
    cudaGetSymbolAddress((void**)&xs,  g_xs);
    cudaGetSymbolAddress((void**)&w16, g_w16);
    cudaGetSymbolAddress((void**)&qs,  g_qs);
    cudaGetSymbolAddress((void**)&kvv, g_kvv);
    cudaGetSymbolAddress((void**)&ct,  g_ct);

    int gemm_smem = G_NSTG * G_STG_B;   // 65536 B
    cudaFuncSetAttribute(gemm_f16_kernel<1>,
                         cudaFuncAttributeMaxDynamicSharedMemorySize, gemm_smem);
    cudaFuncSetAttribute(gemm_f16_kernel<0>,
                         cudaFuncAttributeMaxDynamicSharedMemorySize, gemm_smem);

    // [0] prep: hidden + weights + rope table
    prep_kernel<<<8704, 256>>>(hs, pos, Wq, Wk, Wv, Wo, xs, w16);

    // [1] fused QKV projection with RoPE epilogue (BK=64, 2-stage, 3 CTAs/SM)
    gemm_f16_kernel<1><<<dim3(24, NM / 128), 128, gemm_smem>>>(
        xs, w16, nullptr, qs, kvv, kvv + ASZ);

    // [2] attention (persistent grid 444)
    int attn_smem = 3 * AT_STAGE_B;   // 55296 B
    cudaFuncSetAttribute(attn_tc_kernel,
                         cudaFuncAttributeMaxDynamicSharedMemorySize, attn_smem);
    attn_tc_kernel<<<AT_GRID, 128, attn_smem>>>();

    // [3] output projection (BK=64, 2-stage, 3 CTAs/SM)
    gemm_f16_kernel<0><<<dim3(8, NM / 128), 128, gemm_smem>>>(
        ct, w16 + 3 * WSZ, out, nullptr, nullptr, nullptr);
}

// round 17
// speedup vs baseline: 1.4629x; 1.0013x over previous
#include <cuda_runtime.h>
#include <cuda_bf16.h>
#include <cuda_fp16.h>
#include <math.h>

#define NB   2
#define NS   2048
#define NDM  1024
#define NH   16
#define NDK  64
#define NM   (NB * NS)   // 4096 rows
#define ASZ  ((size_t)NM * NDM)
#define WSZ  ((size_t)NDM * NDM)

// log2(e)/8: folds 1/sqrt(64) attention scale AND exp->ex2 (applied to K)
#define QSCALE 0.18033688011111366f

// Scratch (allocation-free rule: __device__ globals)
__device__ __align__(16) __half g_xs[ASZ];        // hidden states fp16 single
__device__ __align__(16) __half g_w16[4 * WSZ];   // Wq,Wk,Wv,Wo fp16
__device__ __align__(16) __half g_qs[ASZ];        // Q post-rope single fp16
__device__ __align__(16) __half g_kvv[2 * ASZ];   // [K(post-rope,scaled) | V]
__device__ __align__(16) __half g_ct[ASZ];        // ctx single fp16
__device__ __align__(16) float2 g_cs[(size_t)NM * 32];  // rope (cos,sin) table

// ---------------------------------------------------------------------------
// helpers
// ---------------------------------------------------------------------------
__device__ __forceinline__ void ldsm4(unsigned addr, unsigned& r0, unsigned& r1,
                                      unsigned& r2, unsigned& r3)
{
    asm volatile("ldmatrix.sync.aligned.m8n8.x4.shared.b16 {%0,%1,%2,%3}, [%4];"
                 : "=r"(r0), "=r"(r1), "=r"(r2), "=r"(r3) : "r"(addr));
}
__device__ __forceinline__ void ldsm4t(unsigned addr, unsigned& r0, unsigned& r1,
                                       unsigned& r2, unsigned& r3)
{
    asm volatile("ldmatrix.sync.aligned.m8n8.x4.trans.shared.b16 {%0,%1,%2,%3}, [%4];"
                 : "=r"(r0), "=r"(r1), "=r"(r2), "=r"(r3) : "r"(addr));
}
__device__ __forceinline__ void mma_f16(float* d, unsigned a0, unsigned a1,
                                        unsigned a2, unsigned a3,
                                        unsigned b0, unsigned b1)
{
    asm volatile("mma.sync.aligned.m16n8k16.row.col.f32.f16.f16.f32 "
                 "{%0,%1,%2,%3}, {%4,%5,%6,%7}, {%8,%9}, {%0,%1,%2,%3};"
                 : "+f"(d[0]), "+f"(d[1]), "+f"(d[2]), "+f"(d[3])
                 : "r"(a0), "r"(a1), "r"(a2), "r"(a3), "r"(b0), "r"(b1));
}
__device__ __forceinline__ unsigned packhf2(float e0, float e1)
{
    __half2 h = __floats2half2_rn(e0, e1);
    return *reinterpret_cast<unsigned*>(&h);
}
__device__ __forceinline__ unsigned h2exp2u(unsigned x)
{
    unsigned r;
    asm("ex2.approx.f16x2 %0, %1;" : "=r"(r) : "r"(x));
    return r;
}

// ---------------------------------------------------------------------------
// prep: [0..4095] hidden fp32->fp16, [4096..8191] weights fp32->fp16,
//       [8192..8703] rope cos/sin table (pos x 32 freqs)
// ---------------------------------------------------------------------------
__global__ __launch_bounds__(256) void prep_kernel(
    const float* __restrict__ hs, const int* __restrict__ pos,
    const float* __restrict__ w0, const float* __restrict__ w1,
    const float* __restrict__ w2, const float* __restrict__ w3,
    __half* __restrict__ xs, __half* __restrict__ w16)
{
    int b = blockIdx.x;
    if (b < 8192) {
        const float* src;
        __half* dst;
        int loc;
        if (b < 4096) {
            loc = b * 256 + threadIdx.x;
            src = hs; dst = xs;
        } else {
            int i = (b - 4096) * 256 + threadIdx.x;
            int widx = i >> 18;
            loc  = i & ((1 << 18) - 1);
            src = (widx == 0) ? w0 : (widx == 1) ? w1 : (widx == 2) ? w2 : w3;
            dst = w16 + (size_t)widx * WSZ;
        }
        float4 v = reinterpret_cast<const float4*>(src)[loc];
        __half2 h0 = __floats2half2_rn(v.x, v.y);
        __half2 h1 = __floats2half2_rn(v.z, v.w);
        reinterpret_cast<uint2*>(dst)[loc] = make_uint2(*(unsigned*)&h0, *(unsigned*)&h1);
    } else {
        int idx = (b - 8192) * 256 + threadIdx.x;   // [0, 4096*32)
        int m = idx >> 5, i = idx & 31;
        float p = (float)pos[m];
        float freq = (float)exp(-(double)(2 * i) / 64.0 * 9.210340371976184);
        float s, c;
        sincosf(p * freq, &s, &c);
        g_cs[idx] = make_float2(c, s);
    }
}

// ---------------------------------------------------------------------------
// Tensor-core GEMM: Y = A[M,K] * B[N,K]^T, fp16 1-MMA, BK=64 (16 iterations).
// NSTG-stage cp.async ring, per-kernel tuned:
//   QKV (grid 768, multi-wave): NSTG=2, 3 CTAs/SM  (R16 config)
//   Wo  (grid 256, one wave):   NSTG=3, 2 CTAs/SM  (R15 config, 32.2us)
// QKV=1: widx: 0 -> Q (rope, ->g_qs), 1 -> K (rope*QSCALE, ->g_kvv),
//        2 -> V (->g_kvv+ASZ).   QKV=0: f32 out (Wo).
// ---------------------------------------------------------------------------
#define GBK      64
#define G_ROW_B  128                       // bytes per row (64 halfs)
#define G_B_OFF  16384                     // B region after 128 A rows
#define G_STG_B  32768                     // stage bytes

template <int QKV, int NSTG, int MINB>
__global__ __launch_bounds__(128, MINB) void gemm_f16_kernel(
    const __half* __restrict__ A, const __half* __restrict__ Bbase,
    float* __restrict__ Y,
    __half* __restrict__ qs, __half* __restrict__ kvs, __half* __restrict__ v16)
{
    const int K = NDM, N = NDM;
    extern __shared__ __align__(16) __half smem[];

    int t = threadIdx.x;
    int warp = t >> 5, lane = t & 31;
    int wm = warp >> 1, wn = warp & 1;      // 2 x 2 warp grid (64x64 tiles)
    int widx = QKV ? (blockIdx.x >> 3) : 0;
    int nblk = QKV ? (blockIdx.x & 7) : blockIdx.x;
    int m0 = blockIdx.y * 128;
    int n0 = nblk * 128;
    const __half* B = Bbase + (size_t)widx * WSZ;

    unsigned smem_base = (unsigned)__cvta_generic_to_shared(smem);

    // slim cp.async addressing: 2 base pointers + linear strides
    int tr = t >> 3;                        // row base 0..15
    int tc = t & 7;                         // 16B chunk in 128B row
    const __half* gA = A + (size_t)(m0 + tr) * K + tc * 8;
    const __half* gB = B + (size_t)(n0 + tr) * K + tc * 8;
    unsigned sA0 = smem_base + (unsigned)(tr * G_ROW_B + ((tc ^ (tr & 7)) * 16));
    unsigned sB0 = sA0 + G_B_OFF;

#define G_LOAD(soff, koff)                                                    \
    {                                                                         \
        _Pragma("unroll")                                                     \
        for (int j = 0; j < 8; j++)                                           \
            asm volatile("cp.async.cg.shared.global [%0], [%1], 16;"         \
                         :: "r"(sA0 + (soff) + j * (16 * G_ROW_B)),           \
                            "l"(gA + (koff) + (size_t)j * 16 * K));           \
        _Pragma("unroll")                                                     \
        for (int j = 0; j < 8; j++)                                           \
            asm volatile("cp.async.cg.shared.global [%0], [%1], 16;"         \
                         :: "r"(sB0 + (soff) + j * (16 * G_ROW_B)),           \
                            "l"(gB + (koff) + (size_t)j * 16 * K));           \
        asm volatile("cp.async.commit_group;");                               \
    }

    float acc[4][8][4];
#pragma unroll
    for (int mt = 0; mt < 4; mt++)
#pragma unroll
        for (int nt = 0; nt < 8; nt++)
#pragma unroll
            for (int r = 0; r < 4; r++) acc[mt][nt][r] = 0.f;

    // prologue: stages 0..NSTG-2
#pragma unroll
    for (int s = 0; s < NSTG - 1; s++)
        G_LOAD((unsigned)(s * G_STG_B), s * GBK);

    const int NI = NDM / GBK;   // 16
    int cur = 0;                // it % NSTG
    for (int it = 0; it < NI; it++) {
        if (NSTG == 2) {
            asm volatile("cp.async.wait_group 0;");
        } else {
            if (it + 1 < NI) asm volatile("cp.async.wait_group 1;");
            else             asm volatile("cp.async.wait_group 0;");
        }
        __syncthreads();

        if (it + NSTG - 1 < NI) {
            int pf = cur + NSTG - 1; if (pf >= NSTG) pf -= NSTG;
            G_LOAD((unsigned)(pf * G_STG_B), (it + NSTG - 1) * GBK);
        }

        unsigned sb = smem_base + (unsigned)(cur * G_STG_B);
        int lrow = lane & 15;
        int khi  = (lane & 16) ? 8 : 0;

#pragma unroll
        for (int ks = 0; ks < 4; ks++) {
            int kc16 = ((ks * 16 + khi) >> 3);       // 16B chunk index 0..7
            unsigned bh[8][2];
#pragma unroll
            for (int bn = 0; bn < 4; bn++) {
                int nrow = wn * 64 + bn * 16 + lrow;
                unsigned addr = sb + (unsigned)(G_B_OFF + nrow * G_ROW_B
                                    + ((kc16 ^ (nrow & 7)) * 16));
                unsigned r0, r1, r2, r3;
                ldsm4(addr, r0, r1, r2, r3);
                bh[bn * 2][0] = r0; bh[bn * 2 + 1][0] = r1;
                bh[bn * 2][1] = r2; bh[bn * 2 + 1][1] = r3;
            }
#pragma unroll
            for (int mt = 0; mt < 4; mt++) {
                int mrow = wm * 64 + mt * 16 + lrow;
                unsigned addr = sb + (unsigned)(mrow * G_ROW_B
                                    + ((kc16 ^ (mrow & 7)) * 16));
                unsigned a0, a1, a2, a3;
                ldsm4(addr, a0, a1, a2, a3);
#pragma unroll
                for (int nt = 0; nt < 8; nt++)
                    mma_f16(acc[mt][nt], a0, a1, a2, a3, bh[nt][0], bh[nt][1]);
            }
        }
        cur++; if (cur == NSTG) cur = 0;
    }
#undef G_LOAD

    // ---- epilogue ----
#pragma unroll
    for (int mt = 0; mt < 4; mt++) {
        int r = m0 + wm * 64 + mt * 16 + (lane >> 2);
#pragma unroll
        for (int half = 0; half < 2; half++) {
            int gr = r + half * 8;          // global row (b*S + s)
            if (QKV == 0) {
#pragma unroll
                for (int nt = 0; nt < 8; nt++) {
                    int cc = n0 + wn * 64 + nt * 8 + (lane & 3) * 2;
                    size_t idx = (size_t)gr * N + cc;
                    *reinterpret_cast<float2*>(&Y[idx]) =
                        make_float2(acc[mt][nt][half * 2], acc[mt][nt][half * 2 + 1]);
                }
            } else if (widx == 2) {
#pragma unroll
                for (int nt = 0; nt < 8; nt++) {
                    int cc = n0 + wn * 64 + nt * 8 + (lane & 3) * 2;
                    size_t idx = (size_t)gr * N + cc;
                    __half2 h2 = __floats2half2_rn(acc[mt][nt][half * 2],
                                                   acc[mt][nt][half * 2 + 1]);
                    *reinterpret_cast<__half2*>(v16 + idx) = h2;
                }
            } else {
                // RoPE: pair (nt, nt+4) = head-local cols (i, i+32)
#pragma unroll
                for (int nt = 0; nt < 4; nt++) {
                    int hl = nt * 8 + (lane & 3) * 2;       // head-local i, i+1
                    float r1[2], r2[2];
#pragma unroll
                    for (int jj = 0; jj < 2; jj++) {
                        float2 cs = g_cs[(size_t)gr * 32 + hl + jj];
                        float x1 = acc[mt][nt][half * 2 + jj];
                        float x2 = acc[mt][nt + 4][half * 2 + jj];
                        r1[jj] = x1 * cs.x - x2 * cs.y;
                        r2[jj] = x2 * cs.x + x1 * cs.y;
                    }
                    int cc = n0 + wn * 64 + nt * 8 + (lane & 3) * 2;
                    size_t idx = (size_t)gr * N + cc;
                    if (widx == 0) {
                        *reinterpret_cast<__half2*>(qs + idx) =
                            __floats2half2_rn(r1[0], r1[1]);
                        *reinterpret_cast<__half2*>(qs + idx + 32) =
                            __floats2half2_rn(r2[0], r2[1]);
                    } else {
                        *reinterpret_cast<__half2*>(kvs + idx) =
                            __floats2half2_rn(r1[0] * QSCALE, r1[1] * QSCALE);
                        *reinterpret_cast<__half2*>(kvs + idx + 32) =
                            __floats2half2_rn(r2[0] * QSCALE, r2[1] * QSCALE);
                    }
                }
            }
        }
    }
}

// ---------------------------------------------------------------------------
// Tensor-core flash attention, fp16, max-free softmax, 32 q-rows per warp.
// PERSISTENT: grid 444 (=148*3); CTA processes items bid, bid+444 of 512.
// ---------------------------------------------------------------------------
#define AP 72
#define AT_STAGE_E (2 * 64 * AP)
#define AT_STAGE_B (AT_STAGE_E * 2)       // 18432 B
#define K_OFF 0
#define V_OFF (64 * AP)
#define ONES2 0x3C003C00u                 // half2 (1.0, 1.0)
#define AT_GRID 444
#define AT_ITEMS 512                      // 16 qt x 16 h x 2 b

__global__ __launch_bounds__(128, 3) void attn_tc_kernel()
{
    extern __shared__ __align__(16) __half att_smem[];
    unsigned sbase = (unsigned)__cvta_generic_to_shared(att_smem);

    int t = threadIdx.x, lane = t & 31, warp = t >> 5;
    int g = lane >> 2, qr = lane & 3;

    // item-independent smem cp.async destinations + kv offsets
    unsigned goffs[8];
    unsigned sdst[8];
#pragma unroll
    for (int i = 0; i < 8; i++) {
        int gi = t + i * 128;
        int arr = gi >> 9;            // 0=K 1=V
        int rw  = (gi & 511) >> 3;    // key row 0..63
        int c   = gi & 7;             // 16B chunk in 128B row
        goffs[i] = (unsigned)(arr * ASZ + (size_t)rw * NDM + c * 8);
        sdst[i] = sbase + (unsigned)((arr * 64 * AP + rw * AP + c * 8) * 2);
    }

    for (int wi = blockIdx.x; wi < AT_ITEMS; wi += AT_GRID) {
        int qt = wi & 15;
        int h  = (wi >> 4) & 15;
        int b  = wi >> 8;

        // --- Q fragments for this warp's 32 rows (2 m16 halves) ---
        unsigned aQ[2][4][4];
        size_t qbase[2];
#pragma unroll
        for (int mh = 0; mh < 2; mh++) {
            size_t qrow0 = (size_t)(b * NS + qt * 128 + warp * 32 + mh * 16 + g) * NDM
                         + (size_t)h * NDK;
            size_t qrow8 = qrow0 + 8 * NDM;
            qbase[mh] = qrow0;
#pragma unroll
            for (int kk = 0; kk < 4; kk++) {
                int kc = kk * 16 + qr * 2;
                aQ[mh][kk][0] = *reinterpret_cast<const unsigned*>(g_qs + qrow0 + kc);
                aQ[mh][kk][1] = *reinterpret_cast<const unsigned*>(g_qs + qrow8 + kc);
                aQ[mh][kk][2] = *reinterpret_cast<const unsigned*>(g_qs + qrow0 + kc + 8);
                aQ[mh][kk][3] = *reinterpret_cast<const unsigned*>(g_qs + qrow8 + kc + 8);
            }
        }

        const __half* gbase = g_kvv + (size_t)(b * NS) * NDM + (size_t)h * NDK;

        float o[2][8][4];
#pragma unroll
        for (int mh = 0; mh < 2; mh++)
#pragma unroll
            for (int j = 0; j < 8; j++)
#pragma unroll
                for (int r = 0; r < 4; r++) o[mh][j][r] = 0.f;
        float osum[2][4] = {{0.f, 0.f, 0.f, 0.f}, {0.f, 0.f, 0.f, 0.f}};

        // prologue: stages 0 and 1
#pragma unroll
        for (int st = 0; st < 2; st++) {
            unsigned soff = (unsigned)(st * AT_STAGE_B);
            unsigned goff = (unsigned)(st * 64 * NDM);
#pragma unroll
            for (int i = 0; i < 8; i++)
                asm volatile("cp.async.cg.shared.global [%0], [%1], 16;"
                             :: "r"(sdst[i] + soff), "l"(gbase + goffs[i] + goff));
            asm volatile("cp.async.commit_group;");
        }

        const int NT = NS / 64;  // 32
        int cur = 0;
        for (int kt = 0; kt < NT; kt++) {
            if (kt + 1 < NT) asm volatile("cp.async.wait_group 1;");
            else             asm volatile("cp.async.wait_group 0;");
            __syncthreads();

            if (kt + 2 < NT) {
                int pf = cur + 2; if (pf >= 3) pf -= 3;
                unsigned soff = (unsigned)(pf * AT_STAGE_B);
                unsigned goff = (unsigned)((kt + 2) * 64 * NDM);
#pragma unroll
                for (int i = 0; i < 8; i++)
                    asm volatile("cp.async.cg.shared.global [%0], [%1], 16;"
                                 :: "r"(sdst[i] + soff), "l"(gbase + goffs[i] + goff));
                asm volatile("cp.async.commit_group;");
            }

            unsigned sb = sbase + (unsigned)(cur * AT_STAGE_B);
            int lr15 = lane & 15;
            int khi  = (lane & 16) ? 8 : 0;

#pragma unroll
            for (int u = 0; u < 4; u++) {
                float s0[4] = {0.f, 0.f, 0.f, 0.f};
                float s1[4] = {0.f, 0.f, 0.f, 0.f};
                float s2[4] = {0.f, 0.f, 0.f, 0.f};
                float s3[4] = {0.f, 0.f, 0.f, 0.f};
#pragma unroll
                for (int kk = 0; kk < 4; kk++) {
                    unsigned addr = sb + (unsigned)((K_OFF + (u * 16 + lr15) * AP
                                                    + kk * 16 + khi) * 2);
                    unsigned k0, k1, k2, k3;
                    ldsm4(addr, k0, k1, k2, k3);
                    mma_f16(s0, aQ[0][kk][0], aQ[0][kk][1], aQ[0][kk][2], aQ[0][kk][3], k0, k2);
                    mma_f16(s1, aQ[0][kk][0], aQ[0][kk][1], aQ[0][kk][2], aQ[0][kk][3], k1, k3);
                    mma_f16(s2, aQ[1][kk][0], aQ[1][kk][1], aQ[1][kk][2], aQ[1][kk][3], k0, k2);
                    mma_f16(s3, aQ[1][kk][0], aQ[1][kk][1], aQ[1][kk][2], aQ[1][kk][3], k1, k3);
                }

                unsigned ph0[4], ph1[4];
                ph0[0] = h2exp2u(packhf2(s0[0], s0[1]));
                ph0[1] = h2exp2u(packhf2(s0[2], s0[3]));
                ph0[2] = h2exp2u(packhf2(s1[0], s1[1]));
                ph0[3] = h2exp2u(packhf2(s1[2], s1[3]));
                ph1[0] = h2exp2u(packhf2(s2[0], s2[1]));
                ph1[1] = h2exp2u(packhf2(s2[2], s2[3]));
                ph1[2] = h2exp2u(packhf2(s3[0], s3[1]));
                ph1[3] = h2exp2u(packhf2(s3[2], s3[3]));

                mma_f16(osum[0], ph0[0], ph0[1], ph0[2], ph0[3], ONES2, ONES2);
                mma_f16(osum[1], ph1[0], ph1[1], ph1[2], ph1[3], ONES2, ONES2);

#pragma unroll
                for (int n0 = 0; n0 < 64; n0 += 16) {
                    unsigned addr = sb + (unsigned)((V_OFF + (u * 16 + lr15) * AP
                                                    + n0 + ((lane >> 4) & 1) * 8) * 2);
                    unsigned v0, v1, v2, v3;
                    ldsm4t(addr, v0, v1, v2, v3);
                    int j = n0 >> 3;
                    mma_f16(o[0][j],   ph0[0], ph0[1], ph0[2], ph0[3], v0, v1);
                    mma_f16(o[0][j+1], ph0[0], ph0[1], ph0[2], ph0[3], v2, v3);
                    mma_f16(o[1][j],   ph1[0], ph1[1], ph1[2], ph1[3], v0, v1);
                    mma_f16(o[1][j+1], ph1[0], ph1[1], ph1[2], ph1[3], v2, v3);
                }
            }
            cur++; if (cur == 3) cur = 0;
        }

        // ---- epilogue: osum[mh][0]/osum[mh][2] are exact row sums ----
#pragma unroll
        for (int mh = 0; mh < 2; mh++) {
            float inv0 = 1.f / osum[mh][0], inv1 = 1.f / osum[mh][2];
            size_t orow0 = qbase[mh];
            size_t orow8 = orow0 + 8 * NDM;
#pragma unroll
            for (int j = 0; j < 8; j++) {
                int cc = j * 8 + qr * 2;
                __half2 h0 = __floats2half2_rn(o[mh][j][0] * inv0, o[mh][j][1] * inv0);
                __half2 h1 = __floats2half2_rn(o[mh][j][2] * inv1, o[mh][j][3] * inv1);
                *reinterpret_cast<__half2*>(g_ct + orow0 + cc) = h0;
                *reinterpret_cast<__half2*>(g_ct + orow8 + cc) = h1;
            }
        }
        __syncthreads();   // all warps done with smem before next item's prologue
    }
}

// ---------------------------------------------------------------------------
extern "C" void kernel_launch(void* const* d_in, const int* in_sizes, int n_in,
                              void* d_out, int out_size)
{
    const float* hs  = (const float*)d_in[0];
    const int*   pos = (const int*)  d_in[1];
    const float* Wq  = (const float*)d_in[2];
    const float* Wk  = (const float*)d_in[3];
    const float* Wv  = (const float*)d_in[4];
    const float* Wo  = (const float*)d_in[5];
    float* out = (float*)d_out;
    (void)in_sizes; (void)n_in; (void)out_size;

    __half *xs, *w16, *qs, *kvv, *ct;
    cudaGetSymbolAddress((void**)&xs,  g_xs);
    cudaGetSymbolAddress((void**)&w16, g_w16);
    cudaGetSymbolAddress((void**)&qs,  g_qs);
    cudaGetSymbolAddress((void**)&kvv, g_kvv);
    cudaGetSymbolAddress((void**)&ct,  g_ct);

    int qkv_smem = 2 * G_STG_B;   // 65536 B (2-stage)
    int wo_smem  = 3 * G_STG_B;   // 98304 B (3-stage)
    cudaFuncSetAttribute((const void*)gemm_f16_kernel<1, 2, 3>,
                         cudaFuncAttributeMaxDynamicSharedMemorySize, qkv_smem);
    cudaFuncSetAttribute((const void*)gemm_f16_kernel<0, 3, 2>,
                         cudaFuncAttributeMaxDynamicSharedMemorySize, wo_smem);

    // [0] prep: hidden + weights + rope table
    prep_kernel<<<8704, 256>>>(hs, pos, Wq, Wk, Wv, Wo, xs, w16);

    // [1] fused QKV projection with RoPE epilogue (BK=64, 2-stage, 3 CTAs/SM)
    gemm_f16_kernel<1, 2, 3><<<dim3(24, NM / 128), 128, qkv_smem>>>(
        xs, w16, nullptr, qs, kvv, kvv + ASZ);

    // [2] attention (persistent grid 444)
    int attn_smem = 3 * AT_STAGE_B;   // 55296 B
    cudaFuncSetAttribute(attn_tc_kernel,
                         cudaFuncAttributeMaxDynamicSharedMemorySize, attn_smem);
    attn_tc_kernel<<<AT_GRID, 128, attn_smem>>>();

    // [3] output projection (BK=64, 3-stage, 2 CTAs/SM)
    gemm_f16_kernel<0, 3, 2><<<dim3(8, NM / 128), 128, wo_smem>>>(
        ct, w16 + 3 * WSZ, out, nullptr, nullptr, nullptr);
}